// round 2
// baseline (speedup 1.0000x reference)
#include <cuda_runtime.h>

#define BB 32
#define CC 256
#define SS 1024
#define NH 4
#define DH 64
#define NQKV 768

// Scratch (device globals — no allocation allowed in kernel_launch)
__device__ float g_q[BB*NH*SS*DH];   // [b][h][s][d], pre-scaled by 1/8
__device__ float g_k[BB*NH*SS*DH];   // [b][h][s][d]
__device__ float g_v[BB*NH*SS*DH];   // [b][h][s][d]
__device__ float g_o[BB*SS*CC];      // [b][s][h*64+d]

// ---------------------------------------------------------------------------
// Kernel 1: QKV projection.  xs[m][k] = x[b][k][s] (m=b*S+s), W_qkv[k][n].
// 64x64x16 tiles, 256 threads, 4x4 fragments. Scatter to g_q/g_k/g_v.
// ---------------------------------------------------------------------------
__global__ __launch_bounds__(256) void qkv_gemm(
    const float* __restrict__ x, const float* __restrict__ W,
    const float* __restrict__ bias)
{
    __shared__ float As[16][68];  // As[k][m] (68 pad: 16B-aligned rows)
    __shared__ float Bs[16][68];  // Bs[k][n]
    const int m0 = blockIdx.x * 64;
    const int n0 = blockIdx.y * 64;
    const int b  = m0 / SS;
    const int s0 = m0 % SS;
    const int tid = threadIdx.x;
    const int tx = tid & 15, ty = tid >> 4;
    const int lm = tid & 63, lk = tid >> 6;
    const float* xb = x + b * CC * SS;

    float acc[4][4] = {};
    for (int k0 = 0; k0 < CC; k0 += 16) {
        #pragma unroll
        for (int kk = lk; kk < 16; kk += 4) {
            As[kk][lm] = xb[(k0 + kk) * SS + s0 + lm];   // coalesced along s
            Bs[kk][lm] = W[(k0 + kk) * NQKV + n0 + lm];  // coalesced along n
        }
        __syncthreads();
        #pragma unroll
        for (int kk = 0; kk < 16; kk++) {
            float4 a  = *(const float4*)&As[kk][ty * 4];
            float4 bb = *(const float4*)&Bs[kk][tx * 4];
            float av[4] = {a.x, a.y, a.z, a.w};
            float bv[4] = {bb.x, bb.y, bb.z, bb.w};
            #pragma unroll
            for (int i = 0; i < 4; i++)
                #pragma unroll
                for (int j = 0; j < 4; j++)
                    acc[i][j] += av[i] * bv[j];
        }
        __syncthreads();
    }

    #pragma unroll
    for (int i = 0; i < 4; i++) {
        const int s = s0 + ty * 4 + i;
        #pragma unroll
        for (int j = 0; j < 4; j++) {
            const int n = n0 + tx * 4 + j;
            float v = acc[i][j] + bias[n];
            const int head = n / 192;
            const int r = n - head * 192;
            const int sel = r >> 6;
            const int d = r & 63;
            const int idx = ((b * NH + head) * SS + s) * DH + d;
            if (sel == 0)      g_q[idx] = v * 0.125f;  // fold softmax scale
            else if (sel == 1) g_k[idx] = v;
            else               g_v[idx] = v;
        }
    }
}

// ---------------------------------------------------------------------------
// Kernel 2: flash attention per (b,h).  64-query tiles, 32-key tiles,
// online softmax. 256 threads = 16x16; phase1 frag 4x2, phase2 frag 4x4.
// ---------------------------------------------------------------------------
__global__ __launch_bounds__(256) void attn_kernel()
{
    __shared__ float Qs[64][68];  // [q][d]
    __shared__ float Ks[32][65];  // [k][d]  (65: conflict-free phase1 reads)
    __shared__ float Vs[32][68];  // [k][d]  (68: aligned float4 reads)
    __shared__ float Ps[64][33];  // [q][k]
    __shared__ float dummy_pad[16]; // safety slack

    const int q0 = blockIdx.x * 64;
    const int h = blockIdx.y, b = blockIdx.z;
    const float* Qp = g_q + ((size_t)(b * NH + h) * SS) * DH;
    const float* Kp = g_k + ((size_t)(b * NH + h) * SS) * DH;
    const float* Vp = g_v + ((size_t)(b * NH + h) * SS) * DH;
    const int tid = threadIdx.x;
    const int tx = tid & 15, ty = tid >> 4;
    (void)dummy_pad;

    // Load Q tile (64x64) once: 4 float4 per thread.
    #pragma unroll
    for (int t = 0; t < 4; t++) {
        int f = tid + 256 * t;        // float4 index 0..1023
        int row = f >> 4;
        int c4 = (f & 15) * 4;
        float4 v = *(const float4*)&Qp[(q0 + row) * DH + c4];
        *(float4*)&Qs[row][c4] = v;
    }

    float m_i[4], l_i[4], o[4][4];
    #pragma unroll
    for (int i = 0; i < 4; i++) {
        m_i[i] = -1e30f; l_i[i] = 0.f;
        #pragma unroll
        for (int j = 0; j < 4; j++) o[i][j] = 0.f;
    }

    for (int kt = 0; kt < SS; kt += 32) {
        __syncthreads();  // previous phase2 done with Ks/Vs/Ps
        // Load K,V tiles (32x64): 2 float4 each per thread.
        #pragma unroll
        for (int t = 0; t < 2; t++) {
            int f = tid + 256 * t;    // 0..511
            int row = f >> 4;
            int c4 = (f & 15) * 4;
            float4 kv = *(const float4*)&Kp[(kt + row) * DH + c4];
            Ks[row][c4 + 0] = kv.x; Ks[row][c4 + 1] = kv.y;
            Ks[row][c4 + 2] = kv.z; Ks[row][c4 + 3] = kv.w;
            float4 vv = *(const float4*)&Vp[(kt + row) * DH + c4];
            *(float4*)&Vs[row][c4] = vv;
        }
        __syncthreads();

        // Phase 1: scores 64x32, frag 4 rows x 2 cols.
        float sc[4][2] = {};
        #pragma unroll
        for (int kk = 0; kk < 64; kk++) {
            float a0 = Qs[ty * 4 + 0][kk];
            float a1 = Qs[ty * 4 + 1][kk];
            float a2 = Qs[ty * 4 + 2][kk];
            float a3 = Qs[ty * 4 + 3][kk];
            float b0 = Ks[tx * 2 + 0][kk];
            float b1 = Ks[tx * 2 + 1][kk];
            sc[0][0] += a0 * b0; sc[0][1] += a0 * b1;
            sc[1][0] += a1 * b0; sc[1][1] += a1 * b1;
            sc[2][0] += a2 * b0; sc[2][1] += a2 * b1;
            sc[3][0] += a3 * b0; sc[3][1] += a3 * b1;
        }

        // Online softmax update per row (reduce over the 16 tx lanes).
        float rescale[4];
        #pragma unroll
        for (int i = 0; i < 4; i++) {
            float rm = fmaxf(sc[i][0], sc[i][1]);
            #pragma unroll
            for (int off = 8; off >= 1; off >>= 1)
                rm = fmaxf(rm, __shfl_xor_sync(0xffffffffu, rm, off));
            float mnew = fmaxf(m_i[i], rm);
            float scale = __expf(m_i[i] - mnew);
            m_i[i] = mnew;
            float p0 = __expf(sc[i][0] - mnew);
            float p1 = __expf(sc[i][1] - mnew);
            Ps[ty * 4 + i][tx * 2 + 0] = p0;
            Ps[ty * 4 + i][tx * 2 + 1] = p1;
            float rs = p0 + p1;
            #pragma unroll
            for (int off = 8; off >= 1; off >>= 1)
                rs += __shfl_xor_sync(0xffffffffu, rs, off);
            l_i[i] = l_i[i] * scale + rs;
            rescale[i] = scale;
        }
        #pragma unroll
        for (int i = 0; i < 4; i++)
            #pragma unroll
            for (int j = 0; j < 4; j++)
                o[i][j] *= rescale[i];
        __syncthreads();

        // Phase 2: O += P(64x32) @ V(32x64), frag 4 rows x 4 d-cols.
        #pragma unroll
        for (int kk = 0; kk < 32; kk++) {
            float4 v4 = *(const float4*)&Vs[kk][tx * 4];
            float bv[4] = {v4.x, v4.y, v4.z, v4.w};
            float a0 = Ps[ty * 4 + 0][kk];
            float a1 = Ps[ty * 4 + 1][kk];
            float a2 = Ps[ty * 4 + 2][kk];
            float a3 = Ps[ty * 4 + 3][kk];
            #pragma unroll
            for (int j = 0; j < 4; j++) {
                o[0][j] += a0 * bv[j];
                o[1][j] += a1 * bv[j];
                o[2][j] += a2 * bv[j];
                o[3][j] += a3 * bv[j];
            }
        }
    }

    // Write O: g_o[b][s][h*64+d]
    #pragma unroll
    for (int i = 0; i < 4; i++) {
        float inv = 1.0f / l_i[i];
        float4 ov;
        ov.x = o[i][0] * inv; ov.y = o[i][1] * inv;
        ov.z = o[i][2] * inv; ov.w = o[i][3] * inv;
        int s = q0 + ty * 4 + i;
        *(float4*)&g_o[(size_t)(b * SS + s) * CC + h * 64 + tx * 4] = ov;
    }
}

// ---------------------------------------------------------------------------
// Kernel 3: out = O @ W_out + b_out + xs, written transposed to [B,C,H,W].
// Residual xs[b][s][c] = x[b][c][s] — same flat index as the output element.
// ---------------------------------------------------------------------------
__global__ __launch_bounds__(256) void out_gemm(
    const float* __restrict__ x, const float* __restrict__ W,
    const float* __restrict__ bias, float* __restrict__ out)
{
    __shared__ float As[64][20];  // As[m][k] (g_o is row-major over k)
    __shared__ float Bs[16][68];  // Bs[k][n]
    const int m0 = blockIdx.x * 64;
    const int n0 = blockIdx.y * 64;
    const int b  = m0 / SS;
    const int s0 = m0 % SS;
    const int tid = threadIdx.x;
    const int tx = tid & 15, ty = tid >> 4;
    const int lm = tid & 63, lk = tid >> 6;

    float acc[4][4] = {};
    for (int k0 = 0; k0 < CC; k0 += 16) {
        {
            int row = tid >> 2;          // 0..63
            int k4  = (tid & 3) * 4;     // 0,4,8,12
            float4 a = *(const float4*)&g_o[(size_t)(m0 + row) * CC + k0 + k4];
            *(float4*)&As[row][k4] = a;
            #pragma unroll
            for (int kk = lk; kk < 16; kk += 4)
                Bs[kk][lm] = W[(k0 + kk) * CC + n0 + lm];
        }
        __syncthreads();
        #pragma unroll
        for (int kk = 0; kk < 16; kk++) {
            float a0 = As[ty * 4 + 0][kk];
            float a1 = As[ty * 4 + 1][kk];
            float a2 = As[ty * 4 + 2][kk];
            float a3 = As[ty * 4 + 3][kk];
            float4 bb = *(const float4*)&Bs[kk][tx * 4];
            float bv[4] = {bb.x, bb.y, bb.z, bb.w};
            #pragma unroll
            for (int j = 0; j < 4; j++) {
                acc[0][j] += a0 * bv[j];
                acc[1][j] += a1 * bv[j];
                acc[2][j] += a2 * bv[j];
                acc[3][j] += a3 * bv[j];
            }
        }
        __syncthreads();
    }

    #pragma unroll
    for (int i = 0; i < 4; i++) {
        const int s = s0 + ty * 4 + i;
        #pragma unroll
        for (int j = 0; j < 4; j++) {
            const int n = n0 + tx * 4 + j;  // channel
            const size_t idx = ((size_t)b * CC + n) * SS + s;
            out[idx] = acc[i][j] + bias[n] + x[idx];
        }
    }
}

extern "C" void kernel_launch(void* const* d_in, const int* in_sizes, int n_in,
                              void* d_out, int out_size) {
    const float* x    = (const float*)d_in[0];
    const float* Wqkv = (const float*)d_in[1];
    const float* bqkv = (const float*)d_in[2];
    const float* Wout = (const float*)d_in[3];
    const float* bout = (const float*)d_in[4];
    float* out = (float*)d_out;

    dim3 g1(BB * SS / 64, NQKV / 64);   // 512 x 12
    qkv_gemm<<<g1, 256>>>(x, Wqkv, bqkv);

    dim3 g2(SS / 64, NH, BB);           // 16 x 4 x 32
    attn_kernel<<<g2, 256>>>();

    dim3 g3(BB * SS / 64, CC / 64);     // 512 x 4
    out_gemm<<<g3, 256>>>(x, Wout, bout, out);
}

// round 4
// speedup vs baseline: 2.2934x; 2.2934x over previous
#include <cuda_runtime.h>
#include <cuda_bf16.h>

#define BB 32
#define CC 256
#define SS 1024
#define NH 4
#define DH 64
#define NQKV 768

// Scratch (device globals — no allocation allowed)
__device__ __nv_bfloat16 g_q[BB*NH*SS*DH];   // [b][h][s][d], pre-scaled by 1/8
__device__ __nv_bfloat16 g_k[BB*NH*SS*DH];   // [b][h][s][d]
__device__ __nv_bfloat16 g_vt[BB*NH*DH*SS];  // [b][h][d][s]  (transposed V)
__device__ float g_o[BB*SS*CC];              // [b][s][h*64+d]

// ---------------------------------------------------------------------------
// Helpers
// ---------------------------------------------------------------------------
__device__ __forceinline__ void mma16816(float* d, const unsigned* a,
                                         unsigned b0, unsigned b1) {
    asm volatile(
        "mma.sync.aligned.m16n8k16.row.col.f32.bf16.bf16.f32 "
        "{%0,%1,%2,%3}, {%4,%5,%6,%7}, {%8,%9}, {%0,%1,%2,%3};\n"
        : "+f"(d[0]), "+f"(d[1]), "+f"(d[2]), "+f"(d[3])
        : "r"(a[0]), "r"(a[1]), "r"(a[2]), "r"(a[3]), "r"(b0), "r"(b1));
}

__device__ __forceinline__ unsigned pk(float lo, float hi) {
    __nv_bfloat162 t = __float22bfloat162_rn(make_float2(lo, hi));
    return *(unsigned*)&t;
}

__device__ __forceinline__ void cp16(void* smem_dst, const void* gsrc) {
    unsigned saddr = (unsigned)__cvta_generic_to_shared(smem_dst);
    asm volatile("cp.async.cg.shared.global [%0], [%1], 16;\n"
                 :: "r"(saddr), "l"(gsrc));
}
__device__ __forceinline__ void cp_commit() {
    asm volatile("cp.async.commit_group;\n" ::: "memory");
}
template <int N>
__device__ __forceinline__ void cp_wait() {
    asm volatile("cp.async.wait_group %0;\n" :: "n"(N) : "memory");
}

// ---------------------------------------------------------------------------
// Kernel 1: QKV projection (fp32 compute).  xs[m][k] = x[b][k][s], W_qkv[k][n].
// Epilogue writes bf16 Q (scaled), K [s,d], V transposed [d,s].
// ---------------------------------------------------------------------------
__global__ __launch_bounds__(256) void qkv_gemm(
    const float* __restrict__ x, const float* __restrict__ W,
    const float* __restrict__ bias)
{
    __shared__ float As[16][68];
    __shared__ float Bs[16][68];
    const int m0 = blockIdx.x * 64;
    const int n0 = blockIdx.y * 64;
    const int b  = m0 / SS;
    const int s0 = m0 % SS;
    const int tid = threadIdx.x;
    const int tx = tid & 15, ty = tid >> 4;
    const int lm = tid & 63, lk = tid >> 6;
    const float* xb = x + b * CC * SS;

    float acc[4][4] = {};
    for (int k0 = 0; k0 < CC; k0 += 16) {
        #pragma unroll
        for (int kk = lk; kk < 16; kk += 4) {
            As[kk][lm] = xb[(k0 + kk) * SS + s0 + lm];
            Bs[kk][lm] = W[(k0 + kk) * NQKV + n0 + lm];
        }
        __syncthreads();
        #pragma unroll
        for (int kk = 0; kk < 16; kk++) {
            float4 a  = *(const float4*)&As[kk][ty * 4];
            float4 bb = *(const float4*)&Bs[kk][tx * 4];
            float av[4] = {a.x, a.y, a.z, a.w};
            float bv[4] = {bb.x, bb.y, bb.z, bb.w};
            #pragma unroll
            for (int i = 0; i < 4; i++)
                #pragma unroll
                for (int j = 0; j < 4; j++)
                    acc[i][j] += av[i] * bv[j];
        }
        __syncthreads();
    }

    #pragma unroll
    for (int i = 0; i < 4; i++) {
        const int s = s0 + ty * 4 + i;
        #pragma unroll
        for (int j = 0; j < 4; j++) {
            const int n = n0 + tx * 4 + j;
            float v = acc[i][j] + bias[n];
            const int head = n / 192;
            const int r = n - head * 192;
            const int sel = r >> 6;
            const int d = r & 63;
            if (sel == 0)
                g_q[((b*NH + head)*SS + s)*DH + d] = __float2bfloat16(v * 0.125f);
            else if (sel == 1)
                g_k[((b*NH + head)*SS + s)*DH + d] = __float2bfloat16(v);
            else
                g_vt[((b*NH + head)*DH + d)*SS + s] = __float2bfloat16(v);
        }
    }
}

// ---------------------------------------------------------------------------
// Kernel 2: FlashAttention with bf16 mma.sync (m16n8k16), fp32 accum.
// 4 warps / CTA, 64 queries per CTA (16 per warp), 64-key tiles,
// cp.async double-buffered K/V smem, P stays in registers.
// ---------------------------------------------------------------------------
__global__ __launch_bounds__(128) void attn_mma()
{
    __shared__ __align__(16) __nv_bfloat16 Ks[2][64 * 72];
    __shared__ __align__(16) __nv_bfloat16 Vs[2][64 * 72];

    const int q0 = blockIdx.x * 64;
    const int h = blockIdx.y, b = blockIdx.z;
    const size_t bh = (size_t)(b * NH + h);
    const __nv_bfloat16* Qp = g_q  + bh * SS * DH;
    const __nv_bfloat16* Kp = g_k  + bh * SS * DH;
    const __nv_bfloat16* Vp = g_vt + bh * DH * SS;

    const int tid = threadIdx.x;
    const int w = tid >> 5, lane = tid & 31;
    const int g = lane >> 2, tig = lane & 3;
    const int r0 = q0 + w * 16 + g;   // C-frag row (low); high = r0+8

    // Q fragments: 4 k-tiles x 4 b32 regs
    unsigned qa[4][4];
    #pragma unroll
    for (int t = 0; t < 4; t++) {
        const int c = 2 * tig + 16 * t;
        qa[t][0] = *(const unsigned*)(Qp + (size_t)r0 * DH + c);
        qa[t][1] = *(const unsigned*)(Qp + (size_t)(r0 + 8) * DH + c);
        qa[t][2] = *(const unsigned*)(Qp + (size_t)r0 * DH + c + 8);
        qa[t][3] = *(const unsigned*)(Qp + (size_t)(r0 + 8) * DH + c + 8);
    }

    float o[8][4];
    #pragma unroll
    for (int j = 0; j < 8; j++)
        #pragma unroll
        for (int i = 0; i < 4; i++) o[j][i] = 0.f;
    float m0 = -1e30f, m1 = -1e30f, l0 = 0.f, l1 = 0.f;

    // tile loader (cp.async): K tile [kv][d], V tile [d][kv]
    auto loadKV = [&](int kt, int buf) {
        #pragma unroll
        for (int c = 0; c < 4; c++) {
            int lin = c * 1024 + tid * 8;
            int row = lin >> 6, col = lin & 63;
            cp16(&Ks[buf][row * 72 + col], Kp + (size_t)(kt + row) * DH + col);
            cp16(&Vs[buf][row * 72 + col], Vp + (size_t)row * SS + kt + col);
        }
    };

    loadKV(0, 0);
    cp_commit();

    int cur = 0;
    for (int kt = 0; kt < SS; kt += 64) {
        if (kt + 64 < SS) {
            loadKV(kt + 64, cur ^ 1);
            cp_commit();
            cp_wait<1>();
        } else {
            cp_wait<0>();
        }
        __syncthreads();

        // ---- scores: S = Q @ K^T  (per warp: m16 x n64 x k64) ----
        float sc[8][4];
        #pragma unroll
        for (int j = 0; j < 8; j++)
            #pragma unroll
            for (int i = 0; i < 4; i++) sc[j][i] = 0.f;

        #pragma unroll
        for (int t = 0; t < 4; t++) {
            #pragma unroll
            for (int j = 0; j < 8; j++) {
                const int off = (8 * j + g) * 72 + 2 * tig + 16 * t;
                unsigned b0 = *(const unsigned*)&Ks[cur][off];
                unsigned b1 = *(const unsigned*)&Ks[cur][off + 8];
                mma16816(sc[j], qa[t], b0, b1);
            }
        }

        // ---- online softmax (rows r0 and r0+8, spread over 4 tig lanes) ----
        float rm0 = -1e30f, rm1 = -1e30f;
        #pragma unroll
        for (int j = 0; j < 8; j++) {
            rm0 = fmaxf(rm0, fmaxf(sc[j][0], sc[j][1]));
            rm1 = fmaxf(rm1, fmaxf(sc[j][2], sc[j][3]));
        }
        #pragma unroll
        for (int off = 1; off <= 2; off <<= 1) {
            rm0 = fmaxf(rm0, __shfl_xor_sync(0xffffffffu, rm0, off));
            rm1 = fmaxf(rm1, __shfl_xor_sync(0xffffffffu, rm1, off));
        }
        float mn0 = fmaxf(m0, rm0), mn1 = fmaxf(m1, rm1);
        float s0 = __expf(m0 - mn0), s1 = __expf(m1 - mn1);
        m0 = mn0; m1 = mn1;

        float rs0 = 0.f, rs1 = 0.f;
        #pragma unroll
        for (int j = 0; j < 8; j++) {
            sc[j][0] = __expf(sc[j][0] - mn0);
            sc[j][1] = __expf(sc[j][1] - mn0);
            sc[j][2] = __expf(sc[j][2] - mn1);
            sc[j][3] = __expf(sc[j][3] - mn1);
            rs0 += sc[j][0] + sc[j][1];
            rs1 += sc[j][2] + sc[j][3];
        }
        #pragma unroll
        for (int off = 1; off <= 2; off <<= 1) {
            rs0 += __shfl_xor_sync(0xffffffffu, rs0, off);
            rs1 += __shfl_xor_sync(0xffffffffu, rs1, off);
        }
        l0 = l0 * s0 + rs0;
        l1 = l1 * s1 + rs1;
        #pragma unroll
        for (int j = 0; j < 8; j++) {
            o[j][0] *= s0; o[j][1] *= s0;
            o[j][2] *= s1; o[j][3] *= s1;
        }

        // ---- pack P into A-fragments (register-only, FA2 layout trick) ----
        unsigned pa[4][4];
        #pragma unroll
        for (int t = 0; t < 4; t++) {
            pa[t][0] = pk(sc[2*t][0],   sc[2*t][1]);
            pa[t][1] = pk(sc[2*t][2],   sc[2*t][3]);
            pa[t][2] = pk(sc[2*t+1][0], sc[2*t+1][1]);
            pa[t][3] = pk(sc[2*t+1][2], sc[2*t+1][3]);
        }

        // ---- O += P @ V  (V^T in smem [d][kv]) ----
        #pragma unroll
        for (int t = 0; t < 4; t++) {
            #pragma unroll
            for (int j = 0; j < 8; j++) {
                const int off = (8 * j + g) * 72 + 2 * tig + 16 * t;
                unsigned b0 = *(const unsigned*)&Vs[cur][off];
                unsigned b1 = *(const unsigned*)&Vs[cur][off + 8];
                mma16816(o[j], pa[t], b0, b1);
            }
        }

        __syncthreads();
        cur ^= 1;
    }

    // ---- epilogue: normalize and write fp32 O [b][s][h*64+d] ----
    const float inv0 = 1.0f / l0, inv1 = 1.0f / l1;
    float* Ob = g_o + ((size_t)b * SS) * CC + h * 64;
    #pragma unroll
    for (int j = 0; j < 8; j++) {
        const int c = 8 * j + 2 * tig;
        float2 v0 = make_float2(o[j][0] * inv0, o[j][1] * inv0);
        float2 v1 = make_float2(o[j][2] * inv1, o[j][3] * inv1);
        *(float2*)&Ob[(size_t)r0 * CC + c]       = v0;
        *(float2*)&Ob[(size_t)(r0 + 8) * CC + c] = v1;
    }
}

// ---------------------------------------------------------------------------
// Kernel 3: out = O @ W_out + b_out + xs (fp32), written transposed.
// ---------------------------------------------------------------------------
__global__ __launch_bounds__(256) void out_gemm(
    const float* __restrict__ x, const float* __restrict__ W,
    const float* __restrict__ bias, float* __restrict__ out)
{
    __shared__ float As[64][20];
    __shared__ float Bs[16][68];
    const int m0 = blockIdx.x * 64;
    const int n0 = blockIdx.y * 64;
    const int b  = m0 / SS;
    const int s0 = m0 % SS;
    const int tid = threadIdx.x;
    const int tx = tid & 15, ty = tid >> 4;
    const int lm = tid & 63, lk = tid >> 6;

    float acc[4][4] = {};
    for (int k0 = 0; k0 < CC; k0 += 16) {
        {
            int row = tid >> 2;
            int k4  = (tid & 3) * 4;
            float4 a = *(const float4*)&g_o[(size_t)(m0 + row) * CC + k0 + k4];
            *(float4*)&As[row][k4] = a;
            #pragma unroll
            for (int kk = lk; kk < 16; kk += 4)
                Bs[kk][lm] = W[(k0 + kk) * CC + n0 + lm];
        }
        __syncthreads();
        #pragma unroll
        for (int kk = 0; kk < 16; kk++) {
            float a0 = As[ty * 4 + 0][kk];
            float a1 = As[ty * 4 + 1][kk];
            float a2 = As[ty * 4 + 2][kk];
            float a3 = As[ty * 4 + 3][kk];
            float4 bb = *(const float4*)&Bs[kk][tx * 4];
            float bv[4] = {bb.x, bb.y, bb.z, bb.w};
            #pragma unroll
            for (int j = 0; j < 4; j++) {
                acc[0][j] += a0 * bv[j];
                acc[1][j] += a1 * bv[j];
                acc[2][j] += a2 * bv[j];
                acc[3][j] += a3 * bv[j];
            }
        }
        __syncthreads();
    }

    #pragma unroll
    for (int i = 0; i < 4; i++) {
        const int s = s0 + ty * 4 + i;
        #pragma unroll
        for (int j = 0; j < 4; j++) {
            const int n = n0 + tx * 4 + j;
            const size_t idx = ((size_t)b * CC + n) * SS + s;
            out[idx] = acc[i][j] + bias[n] + x[idx];
        }
    }
}

extern "C" void kernel_launch(void* const* d_in, const int* in_sizes, int n_in,
                              void* d_out, int out_size) {
    const float* x    = (const float*)d_in[0];
    const float* Wqkv = (const float*)d_in[1];
    const float* bqkv = (const float*)d_in[2];
    const float* Wout = (const float*)d_in[3];
    const float* bout = (const float*)d_in[4];
    float* out = (float*)d_out;

    dim3 g1(BB * SS / 64, NQKV / 64);
    qkv_gemm<<<g1, 256>>>(x, Wqkv, bqkv);

    dim3 g2(SS / 64, NH, BB);
    attn_mma<<<g2, 128>>>();

    dim3 g3(BB * SS / 64, CC / 64);
    out_gemm<<<g3, 256>>>(x, Wout, bout, out);
}

// round 5
// speedup vs baseline: 4.3136x; 1.8808x over previous
#include <cuda_runtime.h>
#include <cuda_bf16.h>

#define BB 32
#define CC 256
#define SS 1024
#define NH 4
#define DH 64
#define NQKV 768

// Scratch (device globals — no allocation allowed)
__device__ float g_xt[(size_t)BB*SS*CC];       // x transposed [b][s][c], tf32-rounded
__device__ float g_wqt[NQKV*CC];               // W_qkv^T [n][k], tf32-rounded
__device__ float g_wot[CC*CC];                 // W_out^T [n][k], tf32-rounded
__device__ __nv_bfloat16 g_q[BB*NH*SS*DH];     // [b][h][s][d], pre-scaled 1/8
__device__ __nv_bfloat16 g_k[BB*NH*SS*DH];     // [b][h][s][d]
__device__ __nv_bfloat16 g_vt[BB*NH*DH*SS];    // [b][h][d][s]
__device__ float g_o[(size_t)BB*SS*CC];        // [b][s][h*64+d], tf32-rounded

// ---------------------------------------------------------------------------
// Helpers
// ---------------------------------------------------------------------------
__device__ __forceinline__ float tf32r(float f) {
    unsigned u;
    asm("cvt.rna.tf32.f32 %0, %1;" : "=r"(u) : "f"(f));
    return __uint_as_float(u);
}

__device__ __forceinline__ void mma_tf32(float* d, const unsigned* a,
                                         const unsigned* b) {
    asm volatile(
        "mma.sync.aligned.m16n8k8.row.col.f32.tf32.tf32.f32 "
        "{%0,%1,%2,%3}, {%4,%5,%6,%7}, {%8,%9}, {%0,%1,%2,%3};\n"
        : "+f"(d[0]), "+f"(d[1]), "+f"(d[2]), "+f"(d[3])
        : "r"(a[0]), "r"(a[1]), "r"(a[2]), "r"(a[3]), "r"(b[0]), "r"(b[1]));
}

__device__ __forceinline__ void mma16816(float* d, const unsigned* a,
                                         unsigned b0, unsigned b1) {
    asm volatile(
        "mma.sync.aligned.m16n8k16.row.col.f32.bf16.bf16.f32 "
        "{%0,%1,%2,%3}, {%4,%5,%6,%7}, {%8,%9}, {%0,%1,%2,%3};\n"
        : "+f"(d[0]), "+f"(d[1]), "+f"(d[2]), "+f"(d[3])
        : "r"(a[0]), "r"(a[1]), "r"(a[2]), "r"(a[3]), "r"(b0), "r"(b1));
}

__device__ __forceinline__ unsigned pk(float lo, float hi) {
    __nv_bfloat162 t = __float22bfloat162_rn(make_float2(lo, hi));
    return *(unsigned*)&t;
}

__device__ __forceinline__ void cp16(void* smem_dst, const void* gsrc) {
    unsigned saddr = (unsigned)__cvta_generic_to_shared(smem_dst);
    asm volatile("cp.async.cg.shared.global [%0], [%1], 16;\n"
                 :: "r"(saddr), "l"(gsrc));
}
__device__ __forceinline__ void cp_commit() {
    asm volatile("cp.async.commit_group;\n" ::: "memory");
}
template <int N>
__device__ __forceinline__ void cp_wait() {
    asm volatile("cp.async.wait_group %0;\n" :: "n"(N) : "memory");
}

// ---------------------------------------------------------------------------
// Prep: transpose + tf32-round.  src [z][R][C] -> dst [z][C][R]
// ---------------------------------------------------------------------------
__global__ void transpose_tf32(const float* __restrict__ src,
                               float* __restrict__ dst, int R, int C)
{
    __shared__ float t[32][33];
    const int c0 = blockIdx.x * 32, r0 = blockIdx.y * 32;
    const size_t zoff = (size_t)blockIdx.z * R * C;
    const int tx = threadIdx.x, ty = threadIdx.y;
    #pragma unroll
    for (int i = 0; i < 32; i += 8)
        t[ty + i][tx] = tf32r(src[zoff + (size_t)(r0 + ty + i) * C + c0 + tx]);
    __syncthreads();
    #pragma unroll
    for (int i = 0; i < 32; i += 8)
        dst[zoff + (size_t)(c0 + ty + i) * R + r0 + tx] = t[tx][ty + i];
}

// ---------------------------------------------------------------------------
// tf32 GEMM: C[m][n] = A[m][k] @ B[n][k]^T, M-tile 128, N-tile 128, K=256.
// 8 warps, warp tile 64x32. MODE 0: QKV scatter epilogue. MODE 1: out epilogue.
// ---------------------------------------------------------------------------
template <int MODE>
__global__ __launch_bounds__(256) void gemm_tf32(
    const float* __restrict__ A, const float* __restrict__ Bm,
    const float* __restrict__ bias, const float* __restrict__ xres,
    float* __restrict__ out)
{
    __shared__ float As[2][128][20];
    __shared__ float Bs[2][128][20];
    const int m0 = blockIdx.x * 128;
    const int n0 = blockIdx.y * 128;
    const int tid = threadIdx.x;
    const int w = tid >> 5, lane = tid & 31;
    const int g = lane >> 2, tig = lane & 3;
    const int wm = (w & 1) * 64, wn = (w >> 1) * 32;
    const int lrow = tid >> 1;
    const int lcol = (tid & 1) * 8;

    float acc[4][4][4] = {};

    auto load_chunk = [&](int k0, int buf) {
        const float* ap = A + (size_t)(m0 + lrow) * CC + k0 + lcol;
        cp16(&As[buf][lrow][lcol], ap);
        cp16(&As[buf][lrow][lcol + 4], ap + 4);
        const float* bp = Bm + (size_t)(n0 + lrow) * CC + k0 + lcol;
        cp16(&Bs[buf][lrow][lcol], bp);
        cp16(&Bs[buf][lrow][lcol + 4], bp + 4);
    };

    load_chunk(0, 0);
    cp_commit();
    int cur = 0;
    for (int it = 0; it < 16; it++) {
        if (it < 15) { load_chunk((it + 1) * 16, cur ^ 1); cp_commit(); cp_wait<1>(); }
        else cp_wait<0>();
        __syncthreads();
        #pragma unroll
        for (int ks = 0; ks < 16; ks += 8) {
            unsigned a[4][4], b[4][2];
            #pragma unroll
            for (int i = 0; i < 4; i++) {
                a[i][0] = __float_as_uint(As[cur][wm + 16*i + g    ][ks + tig]);
                a[i][1] = __float_as_uint(As[cur][wm + 16*i + g + 8][ks + tig]);
                a[i][2] = __float_as_uint(As[cur][wm + 16*i + g    ][ks + tig + 4]);
                a[i][3] = __float_as_uint(As[cur][wm + 16*i + g + 8][ks + tig + 4]);
            }
            #pragma unroll
            for (int j = 0; j < 4; j++) {
                b[j][0] = __float_as_uint(Bs[cur][wn + 8*j + g][ks + tig]);
                b[j][1] = __float_as_uint(Bs[cur][wn + 8*j + g][ks + tig + 4]);
            }
            #pragma unroll
            for (int i = 0; i < 4; i++)
                #pragma unroll
                for (int j = 0; j < 4; j++)
                    mma_tf32(acc[i][j], a[i], b[j]);
        }
        __syncthreads();
        cur ^= 1;
    }

    const int b_idx = m0 / SS;
    const int s_base = (m0 % SS) + wm + g;

    #pragma unroll
    for (int i = 0; i < 4; i++) {
        #pragma unroll
        for (int j = 0; j < 4; j++) {
            const int n = n0 + wn + 8 * j + 2 * tig;
            const float bs0 = __ldg(&bias[n]);
            const float bs1 = __ldg(&bias[n + 1]);
            #pragma unroll
            for (int half = 0; half < 2; half++) {
                const int s = s_base + 16 * i + 8 * half;
                float v0 = acc[i][j][2 * half]     + bs0;
                float v1 = acc[i][j][2 * half + 1] + bs1;
                if (MODE == 0) {
                    const int head = n / 192;
                    const int r = n - head * 192;
                    const int sel = r >> 6;
                    const int d = r & 63;
                    const size_t bh = (size_t)(b_idx * NH + head);
                    if (sel == 0) {
                        *(__nv_bfloat162*)&g_q[(bh * SS + s) * DH + d] =
                            __float22bfloat162_rn(make_float2(v0 * 0.125f, v1 * 0.125f));
                    } else if (sel == 1) {
                        *(__nv_bfloat162*)&g_k[(bh * SS + s) * DH + d] =
                            __float22bfloat162_rn(make_float2(v0, v1));
                    } else {
                        g_vt[(bh * DH + d)     * SS + s] = __float2bfloat16(v0);
                        g_vt[(bh * DH + d + 1) * SS + s] = __float2bfloat16(v1);
                    }
                } else {
                    const size_t i0 = ((size_t)b_idx * CC + n)     * SS + s;
                    const size_t i1 = ((size_t)b_idx * CC + n + 1) * SS + s;
                    out[i0] = v0 + xres[i0];
                    out[i1] = v1 + xres[i1];
                }
            }
        }
    }
}

// ---------------------------------------------------------------------------
// FlashAttention, bf16 mma.sync (m16n8k16), fp32 accum.  Unchanged from R2
// except epilogue writes tf32-rounded g_o.
// ---------------------------------------------------------------------------
__global__ __launch_bounds__(128) void attn_mma()
{
    __shared__ __align__(16) __nv_bfloat16 Ks[2][64 * 72];
    __shared__ __align__(16) __nv_bfloat16 Vs[2][64 * 72];

    const int q0 = blockIdx.x * 64;
    const int h = blockIdx.y, b = blockIdx.z;
    const size_t bh = (size_t)(b * NH + h);
    const __nv_bfloat16* Qp = g_q  + bh * SS * DH;
    const __nv_bfloat16* Kp = g_k  + bh * SS * DH;
    const __nv_bfloat16* Vp = g_vt + bh * DH * SS;

    const int tid = threadIdx.x;
    const int w = tid >> 5, lane = tid & 31;
    const int g = lane >> 2, tig = lane & 3;
    const int r0 = q0 + w * 16 + g;

    unsigned qa[4][4];
    #pragma unroll
    for (int t = 0; t < 4; t++) {
        const int c = 2 * tig + 16 * t;
        qa[t][0] = *(const unsigned*)(Qp + (size_t)r0 * DH + c);
        qa[t][1] = *(const unsigned*)(Qp + (size_t)(r0 + 8) * DH + c);
        qa[t][2] = *(const unsigned*)(Qp + (size_t)r0 * DH + c + 8);
        qa[t][3] = *(const unsigned*)(Qp + (size_t)(r0 + 8) * DH + c + 8);
    }

    float o[8][4];
    #pragma unroll
    for (int j = 0; j < 8; j++)
        #pragma unroll
        for (int i = 0; i < 4; i++) o[j][i] = 0.f;
    float m0 = -1e30f, m1 = -1e30f, l0 = 0.f, l1 = 0.f;

    auto loadKV = [&](int kt, int buf) {
        #pragma unroll
        for (int c = 0; c < 4; c++) {
            int lin = c * 1024 + tid * 8;
            int row = lin >> 6, col = lin & 63;
            cp16(&Ks[buf][row * 72 + col], Kp + (size_t)(kt + row) * DH + col);
            cp16(&Vs[buf][row * 72 + col], Vp + (size_t)row * SS + kt + col);
        }
    };

    loadKV(0, 0);
    cp_commit();

    int cur = 0;
    for (int kt = 0; kt < SS; kt += 64) {
        if (kt + 64 < SS) { loadKV(kt + 64, cur ^ 1); cp_commit(); cp_wait<1>(); }
        else cp_wait<0>();
        __syncthreads();

        float sc[8][4];
        #pragma unroll
        for (int j = 0; j < 8; j++)
            #pragma unroll
            for (int i = 0; i < 4; i++) sc[j][i] = 0.f;

        #pragma unroll
        for (int t = 0; t < 4; t++) {
            #pragma unroll
            for (int j = 0; j < 8; j++) {
                const int off = (8 * j + g) * 72 + 2 * tig + 16 * t;
                unsigned b0 = *(const unsigned*)&Ks[cur][off];
                unsigned b1 = *(const unsigned*)&Ks[cur][off + 8];
                mma16816(sc[j], qa[t], b0, b1);
            }
        }

        float rm0 = -1e30f, rm1 = -1e30f;
        #pragma unroll
        for (int j = 0; j < 8; j++) {
            rm0 = fmaxf(rm0, fmaxf(sc[j][0], sc[j][1]));
            rm1 = fmaxf(rm1, fmaxf(sc[j][2], sc[j][3]));
        }
        #pragma unroll
        for (int off = 1; off <= 2; off <<= 1) {
            rm0 = fmaxf(rm0, __shfl_xor_sync(0xffffffffu, rm0, off));
            rm1 = fmaxf(rm1, __shfl_xor_sync(0xffffffffu, rm1, off));
        }
        float mn0 = fmaxf(m0, rm0), mn1 = fmaxf(m1, rm1);
        float s0 = __expf(m0 - mn0), s1 = __expf(m1 - mn1);
        m0 = mn0; m1 = mn1;

        float rs0 = 0.f, rs1 = 0.f;
        #pragma unroll
        for (int j = 0; j < 8; j++) {
            sc[j][0] = __expf(sc[j][0] - mn0);
            sc[j][1] = __expf(sc[j][1] - mn0);
            sc[j][2] = __expf(sc[j][2] - mn1);
            sc[j][3] = __expf(sc[j][3] - mn1);
            rs0 += sc[j][0] + sc[j][1];
            rs1 += sc[j][2] + sc[j][3];
        }
        #pragma unroll
        for (int off = 1; off <= 2; off <<= 1) {
            rs0 += __shfl_xor_sync(0xffffffffu, rs0, off);
            rs1 += __shfl_xor_sync(0xffffffffu, rs1, off);
        }
        l0 = l0 * s0 + rs0;
        l1 = l1 * s1 + rs1;
        #pragma unroll
        for (int j = 0; j < 8; j++) {
            o[j][0] *= s0; o[j][1] *= s0;
            o[j][2] *= s1; o[j][3] *= s1;
        }

        unsigned pa[4][4];
        #pragma unroll
        for (int t = 0; t < 4; t++) {
            pa[t][0] = pk(sc[2*t][0],   sc[2*t][1]);
            pa[t][1] = pk(sc[2*t][2],   sc[2*t][3]);
            pa[t][2] = pk(sc[2*t+1][0], sc[2*t+1][1]);
            pa[t][3] = pk(sc[2*t+1][2], sc[2*t+1][3]);
        }

        #pragma unroll
        for (int t = 0; t < 4; t++) {
            #pragma unroll
            for (int j = 0; j < 8; j++) {
                const int off = (8 * j + g) * 72 + 2 * tig + 16 * t;
                unsigned b0 = *(const unsigned*)&Vs[cur][off];
                unsigned b1 = *(const unsigned*)&Vs[cur][off + 8];
                mma16816(o[j], pa[t], b0, b1);
            }
        }

        __syncthreads();
        cur ^= 1;
    }

    const float inv0 = 1.0f / l0, inv1 = 1.0f / l1;
    float* Ob = g_o + ((size_t)b * SS) * CC + h * 64;
    #pragma unroll
    for (int j = 0; j < 8; j++) {
        const int c = 8 * j + 2 * tig;
        float2 v0 = make_float2(tf32r(o[j][0] * inv0), tf32r(o[j][1] * inv0));
        float2 v1 = make_float2(tf32r(o[j][2] * inv1), tf32r(o[j][3] * inv1));
        *(float2*)&Ob[(size_t)r0 * CC + c]       = v0;
        *(float2*)&Ob[(size_t)(r0 + 8) * CC + c] = v1;
    }
}

extern "C" void kernel_launch(void* const* d_in, const int* in_sizes, int n_in,
                              void* d_out, int out_size) {
    const float* x    = (const float*)d_in[0];
    const float* Wqkv = (const float*)d_in[1];
    const float* bqkv = (const float*)d_in[2];
    const float* Wout = (const float*)d_in[3];
    const float* bout = (const float*)d_in[4];
    float* out = (float*)d_out;

    float* xt  = nullptr; cudaGetSymbolAddress((void**)&xt,  g_xt);
    float* wqt = nullptr; cudaGetSymbolAddress((void**)&wqt, g_wqt);
    float* wot = nullptr; cudaGetSymbolAddress((void**)&wot, g_wot);
    float* oo  = nullptr; cudaGetSymbolAddress((void**)&oo,  g_o);

    // Prep: transpose + tf32 rounding
    transpose_tf32<<<dim3(SS/32, CC/32, BB), dim3(32, 8)>>>(x, xt, CC, SS);
    transpose_tf32<<<dim3(NQKV/32, CC/32, 1), dim3(32, 8)>>>(Wqkv, wqt, CC, NQKV);
    transpose_tf32<<<dim3(CC/32, CC/32, 1), dim3(32, 8)>>>(Wout, wot, CC, CC);

    // QKV projection (tf32 tensor cores)
    gemm_tf32<0><<<dim3(BB*SS/128, NQKV/128), 256>>>(xt, wqt, bqkv, nullptr, nullptr);

    // Attention (bf16 tensor cores)
    attn_mma<<<dim3(SS/64, NH, BB), 128>>>();

    // Output projection + residual (tf32 tensor cores)
    gemm_tf32<1><<<dim3(BB*SS/128, CC/128), 256>>>(oo, wot, bout, x, out);
}